// round 16
// baseline (speedup 1.0000x reference)
#include <cuda_runtime.h>
#include <math.h>

#define MAXN 10000

// ---------------- device scratch --------------------------------------------
__device__ float    g_cst;                     // CST_SILU
__device__ float    g_xs[MAXN * 288];          // up-projected node features, [node][slot 0..8][u 0..31]
__device__ float4   g_mid4[MAXN * 288];        // aggregated messages, 1152 f/node
__device__ unsigned g_w3f[8 * 44 * 32 * 2];    // Wr3/8 tf32 B-frags: [nt][ktp 0..3][lane] uint4
__device__ float    g_wr0p[4 * 128];           // Wr0 row-pair packed
__device__ float    g_wr1p[32 * 128];          // Wr1 row-pair packed
__device__ float    g_wr2p[32 * 128];          // Wr2 row-pair packed

// row-pair packing: p[j2*128 + lane*4 + c]:
//   c0 = W[2j2][2*lane], c1 = W[2j2][2*lane+1], c2 = W[2j2+1][2*lane], c3 = W[2j2+1][2*lane+1]
// g_w3f uint4 at ((nt*4+ktp)*32+lane): {b0(kt=2ktp), b1(2ktp), b0(2ktp+1), b1(2ktp+1)}
//
// g_xs per-node layout (288 floats): slot*32 + u, slot = {x0, x1_0..2, x2_0..4}
// g_mid per-node layout (1152 floats), u-major float4 groups:
//   blk0 A:    u*4 + {p0, p1, p2, p74}
//   blk1..4 B: 128 + q*128 + u*4 + {x, y, z, extra_q}, extra = {p84, p94, pa4, 0}
//   blk5..8 C: 640 + r*128 + u*4 + c

typedef unsigned long long ull;

__device__ __forceinline__ float silu_f(float v) {
    return __fdividef(v, 1.0f + __expf(-v));
}

#define FFMA2(d, a, b) asm("fma.rn.f32x2 %0, %1, %2, %3;" : "=l"(d) : "l"(a), "l"(b), "l"(d))

__device__ __forceinline__ float2 upk(ull v) {
    float2 r;
    asm("mov.b64 {%0, %1}, %2;" : "=f"(r.x), "=f"(r.y) : "l"(v));
    return r;
}

__device__ __forceinline__ unsigned tf32_rna(float x) {
    unsigned u;
    asm("cvt.rna.tf32.f32 %0, %1;" : "=r"(u) : "f"(x));
    return u;
}

__device__ __forceinline__ void mma_tf32(float& c0, float& c1, float& c2, float& c3,
                                         unsigned a0, unsigned a1, unsigned a2, unsigned a3,
                                         unsigned b0, unsigned b1) {
    asm volatile(
        "mma.sync.aligned.m16n8k8.row.col.f32.tf32.tf32.f32 "
        "{%0,%1,%2,%3},{%4,%5,%6,%7},{%8,%9},{%0,%1,%2,%3};"
        : "+f"(c0), "+f"(c1), "+f"(c2), "+f"(c3)
        : "r"(a0), "r"(a1), "r"(a2), "r"(a3), "r"(b0), "r"(b1));
}

// ---------------- fused prep -------------------------------------------------
// b=0: cst | b in [1,44]: w3f repack | b=45: Wr0/1/2 row-pair repack | b>=46: zero mid
__global__ void prep_kernel(const float* __restrict__ Wr0,
                            const float* __restrict__ Wr1,
                            const float* __restrict__ Wr2,
                            const float* __restrict__ Wr3, int n4zero) {
    const int b = blockIdx.x;
    const int t = threadIdx.x;  // 256

    if (b == 0) {
        __shared__ double red[256];
        const int NI = 4096;
        const double h = 24.0 / NI;
        double s = 0.0;
        for (int i = t; i <= NI; i += 256) {
            double xx = -12.0 + h * i;
            double sig = 1.0 / (1.0 + exp(-xx));
            double f = xx * sig;
            f = f * f * exp(-0.5 * xx * xx);
            double c = (i == 0 || i == NI) ? 1.0 : ((i & 1) ? 4.0 : 2.0);
            s += c * f;
        }
        red[t] = s;
        __syncthreads();
        for (int o = 128; o > 0; o >>= 1) {
            if (t < o) red[t] += red[t + o];
            __syncthreads();
        }
        if (t == 0) {
            double I = red[0] * h / 3.0 / 2.5066282746310005024;
            g_cst = (float)(1.0 / sqrt(I));
        }
    } else if (b <= 44) {
        const int f = (b - 1) * 256 + t;   // (kt*44 + nt)*32 + lane
        if (f < 8 * 44 * 32) {
            const int lane = f & 31;
            const int pair = f >> 5;
            const int nt = pair % 44;
            const int kt = pair / 44;
            const int tig = lane & 3;
            const int gid = lane >> 2;
            const int n = nt * 8 + gid;
            float w0 = Wr3[(kt * 8 + tig) * 352 + n] * 0.125f;
            float w1 = Wr3[(kt * 8 + tig + 4) * 352 + n] * 0.125f;
            const int ktp = kt >> 1;
            const int o = (((nt * 4 + ktp) * 32 + lane) << 2) + ((kt & 1) << 1);
            g_w3f[o + 0] = tf32_rna(w0);
            g_w3f[o + 1] = tf32_rna(w1);
        }
    } else if (b == 45) {
        // Wr0/1/2 row-pair repack: 512 + 4096 + 4096 = 8704 elements
        for (int idx = t; idx < 8704; idx += 256) {
            const float* W;
            float* P;
            int li;
            if (idx < 512)       { W = Wr0; P = g_wr0p; li = idx; }
            else if (idx < 4608) { W = Wr1; P = g_wr1p; li = idx - 512; }
            else                 { W = Wr2; P = g_wr2p; li = idx - 4608; }
            const int j2 = li >> 7, q = li & 127;
            const int lane = q >> 2, c = q & 3;
            const int row = 2 * j2 + (c >> 1);
            const int col = 2 * lane + (c & 1);
            P[li] = W[row * 64 + col];
        }
    } else {
        const int i = (b - 46) * 256 + t;
        if (i < n4zero) g_mid4[i] = make_float4(0.f, 0.f, 0.f, 0.f);
    }
}

// ---------------- node up-projection (8 nodes/block, slot-major) ------------
__global__ void up_kernel(const float* __restrict__ f_in,
                          const float* __restrict__ Wu0,
                          const float* __restrict__ Wu1,
                          const float* __restrict__ Wu2, int N) {
    const int n0 = blockIdx.x * 8;
    const int t = threadIdx.x;  // 288
    __shared__ float fs[8][288];
    const int nmax = (N - n0 < 8) ? (N - n0) : 8;
#pragma unroll 1
    for (int j = t; j < nmax * 288; j += 288)
        fs[j / 288][j % 288] = f_in[n0 * 288 + j];
    __syncthreads();

    const int slot = t >> 5;
    const int w = t & 31;
    int i, off, d;
    const float* W;
    if (slot == 0)      { i = 0;        d = 1; off = 0;   W = Wu0; }
    else if (slot < 4)  { i = slot - 1; d = 3; off = 32;  W = Wu1; }
    else                { i = slot - 4; d = 5; off = 128; W = Wu2; }

    float acc[8] = {0.f, 0.f, 0.f, 0.f, 0.f, 0.f, 0.f, 0.f};
#pragma unroll 4
    for (int u = 0; u < 32; u++) {
        float wt = __ldg(W + u * 32 + w);
        const int fi = off + u * d + i;
#pragma unroll
        for (int e = 0; e < 8; e++)
            acc[e] = fmaf(fs[e][fi], wt, acc[e]);
    }
#pragma unroll
    for (int e = 0; e < nmax; e++)
        g_xs[(n0 + e) * 288 + slot * 32 + w] = acc[e] * 0.17677669529663687f;
}

// ---------------- radial MLP 64->64 layer (4 edges, packed weights) ---------
__device__ __forceinline__ void mlp64d(const float* __restrict__ in2,
                                       float* __restrict__ out2,
                                       const float* __restrict__ Wp,
                                       int lane, float cst) {
    ull accA[4] = {0ull,0ull,0ull,0ull};
    ull accB[4] = {0ull,0ull,0ull,0ull};
    const ulonglong2* Wpp = reinterpret_cast<const ulonglong2*>(Wp + lane * 4);
#pragma unroll 4
    for (int j2 = 0; j2 < 32; j2++) {
        ulonglong2 wp = __ldg(Wpp + j2 * 32);   // one LDG.128, 512B contiguous per warp
#pragma unroll
        for (int e = 0; e < 4; e++) {
            ulonglong2 hp = *reinterpret_cast<const ulonglong2*>(in2 + e * 128 + 4 * j2);
            FFMA2(accA[e], wp.x, hp.x);
            FFMA2(accB[e], wp.y, hp.y);
        }
    }
#pragma unroll
    for (int e = 0; e < 4; e++) {
        float2 va = upk(accA[e]);
        float2 vb = upk(accB[e]);
        float v0 = silu_f((va.x + vb.x) * 0.125f) * cst;
        float v1 = silu_f((va.y + vb.y) * 0.125f) * cst;
        *reinterpret_cast<float4*>(out2 + e * 128 + 4 * lane) = make_float4(v0, v0, v1, v1);
    }
}

// smem layout (floats), hfr aliased under wsm (3-barrier structure):
//   phase 1: hA2 [0,4096)  hB2 [4096,8192)  hfr [8192,10304)
//   phase 2+: wsm [0, 11584) = [32 edges][stride 362]  (clobbers all of the above)
//   geo  [11584, 11744)    per-warp edge state, survives whole kernel
#define SM_HA 0
#define SM_HB 4096
#define SM_HF 8192
#define SM_GEO 11584
#define WS_STRIDE 362
#define SM_TOTAL_F 11744

// ---------------- fused per-edge kernel (block = 32 edges) ------------------
__global__ void __launch_bounds__(256, 3) edge_kernel(
    const float* __restrict__ pos, const int* __restrict__ batch,
    const int* __restrict__ esrc, const int* __restrict__ edst,
    const float* __restrict__ shifts, const float* __restrict__ cell, int E)
{
    extern __shared__ float sm[];
    const int wid  = threadIdx.x >> 5;
    const int lane = threadIdx.x & 31;
    float* hA2 = sm + SM_HA + wid * 512;
    float* hB2 = sm + SM_HB + wid * 512;
    unsigned* hfr = reinterpret_cast<unsigned*>(sm + SM_HF);
    float* geo = sm + SM_GEO + wid * 20;   // [4 edges][5]
    float* wsm = sm;                       // aliases hA2/hB2/hfr after handoff

    const int base = blockIdx.x * 32 + wid * 4;
    const int etile = wid >> 2;
    const float cst = g_cst;

    // ================= phase 1: geometry + radial MLP layers 1-3 ============
    {
        float Lr[4];
#pragma unroll
        for (int e = 0; e < 4; e++) {
            int ei = (base + e < E) ? base + e : E - 1;
            const int src = __ldg(esrc + ei);
            const int dst = __ldg(edst + ei);
            const float sx = __ldg(shifts + 3*ei), sy = __ldg(shifts + 3*ei+1), sz = __ldg(shifts + 3*ei+2);
            const float* Cc = cell + 9 * __ldg(batch + src);
            float vx = __ldg(pos+3*dst+0) - __ldg(pos+3*src+0) + sx*__ldg(Cc+0) + sy*__ldg(Cc+3) + sz*__ldg(Cc+6);
            float vy = __ldg(pos+3*dst+1) - __ldg(pos+3*src+1) + sx*__ldg(Cc+1) + sy*__ldg(Cc+4) + sz*__ldg(Cc+7);
            float vz = __ldg(pos+3*dst+2) - __ldg(pos+3*src+2) + sx*__ldg(Cc+2) + sy*__ldg(Cc+5) + sz*__ldg(Cc+8);
            float L = sqrtf(vx*vx + vy*vy + vz*vz);
            float inv = 1.0f / fmaxf(L, 1e-12f);
            Lr[e] = L;
            if (lane == 0) {
                geo[e * 5 + 0] = vx * inv;
                geo[e * 5 + 1] = vy * inv;
                geo[e * 5 + 2] = vz * inv;
                geo[e * 5 + 3] = __int_as_float(src);
                geo[e * 5 + 4] = __int_as_float(dst);
            }
        }

        const int k = lane & 7;
        const int e = lane >> 3;
        float Ls = Lr[0];
        if (e == 1) Ls = Lr[1]; else if (e == 2) Ls = Lr[2]; else if (e == 3) Ls = Lr[3];
        float tt = (Ls - (float)(k + 1) * (5.0f / 9.0f)) * 1.8f;
        float v = __expf(-tt * tt) * 2.525381361380527f;  // sqrt(8)/1.12
        *reinterpret_cast<float2*>(hB2 + e * 128 + 2 * k) = make_float2(v, v);
    }
    __syncwarp();

    // layer 1: 8 -> 64 (hB2 -> hA2), packed weights
    {
        ull acc[4] = {0ull,0ull,0ull,0ull};
        const ulonglong2* Wpp = reinterpret_cast<const ulonglong2*>(g_wr0p + lane * 4);
#pragma unroll
        for (int j2 = 0; j2 < 4; j2++) {
            ulonglong2 wp = __ldg(Wpp + j2 * 32);
#pragma unroll
            for (int e = 0; e < 4; e++) {
                ulonglong2 hp = *reinterpret_cast<const ulonglong2*>(hB2 + e * 128 + 4 * j2);
                FFMA2(acc[e], wp.x, hp.x);
                FFMA2(acc[e], wp.y, hp.y);
            }
        }
#pragma unroll
        for (int e = 0; e < 4; e++) {
            float2 v = upk(acc[e]);
            float v0 = silu_f(v.x * 0.35355339059327373f) * cst;
            float v1 = silu_f(v.y * 0.35355339059327373f) * cst;
            *reinterpret_cast<float4*>(hA2 + e * 128 + 4 * lane) = make_float4(v0, v0, v1, v1);
        }
    }
    __syncwarp();
    mlp64d(hA2, hB2, g_wr1p, lane, cst);   // layer 2
    __syncwarp();

    // layer 3: read hB2, write h into A-fragment layout (tf32 bits)
    {
        ull accA[4] = {0ull,0ull,0ull,0ull};
        ull accB[4] = {0ull,0ull,0ull,0ull};
        const ulonglong2* Wpp = reinterpret_cast<const ulonglong2*>(g_wr2p + lane * 4);
#pragma unroll 4
        for (int j2 = 0; j2 < 32; j2++) {
            ulonglong2 wp = __ldg(Wpp + j2 * 32);
#pragma unroll
            for (int e = 0; e < 4; e++) {
                ulonglong2 hp = *reinterpret_cast<const ulonglong2*>(hB2 + e * 128 + 4 * j2);
                FFMA2(accA[e], wp.x, hp.x);
                FFMA2(accB[e], wp.y, hp.y);
            }
        }
#pragma unroll
        for (int e = 0; e < 4; e++) {
            float2 va = upk(accA[e]);
            float2 vb = upk(accB[e]);
            float v0 = silu_f((va.x + vb.x) * 0.125f) * cst;
            float v1 = silu_f((va.y + vb.y) * 0.125f) * cst;
            const int m = (wid & 3) * 4 + e;
#pragma unroll
            for (int cc = 0; cc < 2; cc++) {
                int k  = 2 * lane + cc;
                float v = cc ? v1 : v0;
                int kt  = k >> 3;
                int kin = k & 7;
                int reg = ((m >= 8) ? 1 : 0) + ((kin >= 4) ? 2 : 0);
                int lp  = (m & 7) * 4 + (kin & 3);
                hfr[((etile * 8 + kt) * 4 + reg) * 33 + lp] = tf32_rna(v);
            }
        }
    }
    __syncthreads();   // hfr complete across etile

    // ================= fragment handoff =====================================
    unsigned afr[8][4];
#pragma unroll
    for (int kt = 0; kt < 8; kt++)
#pragma unroll
        for (int r = 0; r < 4; r++)
            afr[kt][r] = hfr[((etile * 8 + kt) * 4 + r) * 33 + lane];
    __syncthreads();   // fragments in regs; smem freed for wsm

    // ================= MMA pass: all 44 n-tiles =============================
    {
        const int nch = wid & 3;
        const int gid = lane >> 2;
        const int tig = lane & 3;
        const uint4* Bf4 = reinterpret_cast<const uint4*>(g_w3f);
#pragma unroll 1
        for (int tt = 0; tt < 11; tt++) {
            const int nt = nch * 11 + tt;
            float c0 = 0.f, c1 = 0.f, c2 = 0.f, c3 = 0.f;
#pragma unroll
            for (int ktp = 0; ktp < 4; ktp++) {
                uint4 q = __ldg(Bf4 + (nt * 4 + ktp) * 32 + lane);  // 512B contiguous/warp
                mma_tf32(c0, c1, c2, c3,
                         afr[2*ktp][0], afr[2*ktp][1], afr[2*ktp][2], afr[2*ktp][3],
                         q.x, q.y);
                mma_tf32(c0, c1, c2, c3,
                         afr[2*ktp+1][0], afr[2*ktp+1][1], afr[2*ktp+1][2], afr[2*ktp+1][3],
                         q.z, q.w);
            }
            const int col = nt * 8 + tig * 2;
            float* r0 = wsm + (etile * 16 + gid) * WS_STRIDE + col;
            *reinterpret_cast<float2*>(r0) = make_float2(c0, c1);
            *reinterpret_cast<float2*>(r0 + 8 * WS_STRIDE) = make_float2(c2, c3);
        }
    }
    __syncthreads();

    // ================= TP + 9 coalesced vector atomics ======================
    const float A_  = 0.31622776601683794f;  // 1/sqrt(10)
    const float B_  = 0.18257418583505536f;  // 1/sqrt(30)
    const float AL  = 0.11952286093343936f;  // 1/sqrt(70)
    const float BE  = 0.20701966780270626f;  // sqrt(3/70)
    const float SQ3 = 1.7320508075688772f;
    const float SQ5 = 2.23606797749979f;

#pragma unroll 1
    for (int e = 0; e < 4; e++) {
        if (base + e >= E) break;
        const float ux = geo[e * 5 + 0];
        const float uy = geo[e * 5 + 1];
        const float uz = geo[e * 5 + 2];
        const int src = __float_as_int(geo[e * 5 + 3]);
        const int dst = __float_as_int(geo[e * 5 + 4]);

        const float s1x = SQ3 * ux, s1y = SQ3 * uy, s1z = SQ3 * uz;
        const float s20 = 3.872983346207417f * ux * uz;
        const float s21 = 3.872983346207417f * ux * uy;
        const float s22 = SQ5 * (uy*uy - 0.5f*(ux*ux + uz*uz));
        const float s23 = 3.872983346207417f * uy * uz;
        const float s24 = 1.9364916731037085f * (uz*uz - ux*ux);

        const float* wrow = wsm + (wid * 4 + e) * WS_STRIDE + lane;
        float w[11];
#pragma unroll
        for (int k = 0; k < 11; k++) w[k] = wrow[k * 32];

        const float* xp = g_xs + src * 288 + lane;
        const float x0  = __ldg(xp);
        const float x10 = __ldg(xp + 32),  x11 = __ldg(xp + 64),  x12 = __ldg(xp + 96);
        const float x20 = __ldg(xp + 128), x21 = __ldg(xp + 160), x22 = __ldg(xp + 192);
        const float x23 = __ldg(xp + 224), x24 = __ldg(xp + 256);

        // l0
        const float p0 = x0 * w[0];
        const float p1 = 0.5773502691896258f * (x10*s1x + x11*s1y + x12*s1z) * w[1];
        const float p2 = 0.4472135954999579f * (x20*s20 + x21*s21 + x22*s22 + x23*s23 + x24*s24) * w[2];

        // l1
        const float c3 = x0 * w[3];
        float p5x, p5y, p5z;
        {
            float wv = SQ3 * w[5];
            float B00 = -B_*s22 - A_*s24;
            float B01 =  A_*s21;
            float B02 =  A_*s20;
            float B11 =  2.f*B_*s22;
            float B12 =  A_*s23;
            float B22 = -B_*s22 + A_*s24;
            p5x = wv * (x10*B00 + x11*B01 + x12*B02);
            p5y = wv * (x10*B01 + x11*B11 + x12*B12);
            p5z = wv * (x10*B02 + x11*B12 + x12*B22);
        }
        float p6x, p6y, p6z;
        {
            float wv = SQ3 * w[6];
            p6x = wv * (A_*(x20*s1z + x21*s1y) - B_*x22*s1x - A_*x24*s1x);
            p6y = wv * (A_*(x21*s1x + x23*s1z) + 2.f*B_*x22*s1y);
            p6z = wv * (A_*(x20*s1x + x23*s1y + x24*s1z) - B_*x22*s1z);
        }

        // l2
        const float c7 = x0 * w[7];
        const float p70 = c7*s20, p71 = c7*s21, p72 = c7*s22, p73 = c7*s23, p74 = c7*s24;
        float p80, p81, p82, p83, p84;
        {
            float wv = SQ5 * w[8];
            p80 = wv * (A_*(x10*s1z + x12*s1x));
            p81 = wv * (A_*(x10*s1y + x11*s1x));
            p82 = wv * (B_*(-x10*s1x + 2.f*x11*s1y - x12*s1z));
            p83 = wv * (A_*(x11*s1z + x12*s1y));
            p84 = wv * (A_*(-x10*s1x + x12*s1z));
        }
        const float p90 = x20*w[9], p91 = x21*w[9], p92 = x22*w[9], p93 = x23*w[9], p94 = x24*w[9];
        float pa0, pa1, pa2, pa3, pa4;
        {
            float wv = SQ5 * w[10];
            pa0 = wv * (x20*(2.f*AL*s22) + x21*(-BE*s23) + x22*(2.f*AL*s20) + x23*(-BE*s21));
            pa1 = wv * (x20*(-BE*s23) + x21*(-AL*s22 + BE*s24) + x22*(-AL*s21) + x23*(-BE*s20) + x24*(BE*s21));
            pa2 = wv * (x20*(2.f*AL*s20) + x21*(-AL*s21) + x22*(-2.f*AL*s22) + x23*(-AL*s23) + x24*(2.f*AL*s24));
            pa3 = wv * (x20*(-BE*s21) + x21*(-BE*s20) + x22*(-AL*s23) + x23*(-AL*s22 - BE*s24) + x24*(-BE*s23));
            pa4 = wv * (x21*(BE*s21) + x22*(2.f*AL*s24) + x23*(-BE*s23) + x24*(2.f*AL*s22));
        }

        float4* mb = reinterpret_cast<float4*>(reinterpret_cast<float*>(g_mid4) + dst * 1152) + lane;
        atomicAdd(mb,       make_float4(p0, p1, p2, p74));
        atomicAdd(mb + 32,  make_float4(c3*s1x, c3*s1y, c3*s1z, p84));
        atomicAdd(mb + 64,  make_float4(x10*w[4], x11*w[4], x12*w[4], p94));
        atomicAdd(mb + 96,  make_float4(p5x, p5y, p5z, pa4));
        atomicAdd(mb + 128, make_float4(p6x, p6y, p6z, 0.f));
        atomicAdd(mb + 160, make_float4(p70, p71, p72, p73));
        atomicAdd(mb + 192, make_float4(p80, p81, p82, p83));
        atomicAdd(mb + 224, make_float4(p90, p91, p92, p93));
        atomicAdd(mb + 256, make_float4(pa0, pa1, pa2, pa3));
    }
}

// ---------------- per-node output projection (8 nodes/block, transposed) ----
__global__ void out_kernel(const float* __restrict__ Wo0,
                           const float* __restrict__ Wo1,
                           const float* __restrict__ Wo2,
                           float* __restrict__ out, int N) {
    const int n0 = blockIdx.x * 8;
    const int t = threadIdx.x;  // 288
    __shared__ float ms[8][1152];
    const int nmax = (N - n0 < 8) ? (N - n0) : 8;
#pragma unroll 1
    for (int j = t; j < nmax * 288; j += 288) {
        const int node = j / 288, jj = j % 288;
        float4 v = g_mid4[(n0 + node) * 288 + jj];
        const int blk = jj >> 5, u = jj & 31;
        float* b = ms[node] + (blk * 4) * 32 + u;
        b[0]  = v.x;
        b[32] = v.y;
        b[64] = v.z;
        b[96] = v.w;
    }
    __syncthreads();

    const int slot = t >> 5;
    const int w = t & 31;
    float acc[8] = {0.f, 0.f, 0.f, 0.f, 0.f, 0.f, 0.f, 0.f};
    int off, d, i;
    float scale;

    #define OUT_ACC(Wp, grp, sidx)                                             \
        do {                                                                   \
            const float4* mrow[8];                                             \
            _Pragma("unroll")                                                  \
            for (int e = 0; e < 8; e++)                                        \
                mrow[e] = reinterpret_cast<const float4*>(ms[e] + (sidx) * 32);\
            _Pragma("unroll")                                                  \
            for (int u4 = 0; u4 < 8; u4++) {                                   \
                float4 mv[8];                                                  \
                _Pragma("unroll")                                              \
                for (int e = 0; e < 8; e++) mv[e] = mrow[e][u4];               \
                _Pragma("unroll")                                              \
                for (int c = 0; c < 4; c++) {                                  \
                    float wt = __ldg(Wp + ((grp) * 32 + u4 * 4 + c) * 32 + w); \
                    _Pragma("unroll")                                          \
                    for (int e = 0; e < 8; e++) {                              \
                        float mval = (c == 0) ? mv[e].x : (c == 1) ? mv[e].y   \
                                   : (c == 2) ? mv[e].z : mv[e].w;             \
                        acc[e] = fmaf(mval, wt, acc[e]);                       \
                    }                                                          \
                }                                                              \
            }                                                                  \
        } while (0)

    if (slot == 0) {
        off = 0; d = 1; i = 0;
        scale = 0.006378879538497859f;   // 1/(sqrt(96)*16)
#pragma unroll
        for (int s = 0; s < 3; s++)
            OUT_ACC(Wo0, s, s);
    } else if (slot < 4) {
        off = 32; d = 3; i = slot - 1;
        scale = 0.005524271728019903f;   // 1/(sqrt(128)*16)
#pragma unroll
        for (int q = 0; q < 4; q++)
            OUT_ACC(Wo1, q, 4 + q * 4 + i);
    } else {
        off = 128; d = 5; i = slot - 4;
        scale = 0.005524271728019903f;
        if (i < 4) {
#pragma unroll
            for (int r = 0; r < 4; r++)
                OUT_ACC(Wo2, r, 20 + r * 4 + i);
        } else {
#pragma unroll
            for (int r = 0; r < 4; r++)
                OUT_ACC(Wo2, r, 4 * r + 3);
        }
    }
    #undef OUT_ACC

#pragma unroll
    for (int e = 0; e < nmax; e++)
        out[(n0 + e) * 288 + off + w * d + i] = acc[e] * scale;
}

// ---------------- launch -----------------------------------------------------
extern "C" void kernel_launch(void* const* d_in, const int* in_sizes, int n_in,
                              void* d_out, int out_size) {
    const float* f_in   = (const float*)d_in[0];
    const float* pos    = (const float*)d_in[1];
    const int*   batch  = (const int*)d_in[2];
    const int*   esrc   = (const int*)d_in[3];
    const int*   edst   = (const int*)d_in[4];
    const float* shifts = (const float*)d_in[5];
    const float* cell   = (const float*)d_in[6];
    const int wb = n_in - 10;
    const float* Wu0 = (const float*)d_in[wb + 0];
    const float* Wu1 = (const float*)d_in[wb + 1];
    const float* Wu2 = (const float*)d_in[wb + 2];
    const float* Wr0 = (const float*)d_in[wb + 3];
    const float* Wr1 = (const float*)d_in[wb + 4];
    const float* Wr2 = (const float*)d_in[wb + 5];
    const float* Wr3 = (const float*)d_in[wb + 6];
    const float* Wo0 = (const float*)d_in[wb + 7];
    const float* Wo1 = (const float*)d_in[wb + 8];
    const float* Wo2 = (const float*)d_in[wb + 9];

    const int N = in_sizes[0] / 288;
    const int E = in_sizes[3];

    static int smem_set = 0;
    const int smem_bytes = SM_TOTAL_F * 4;  // 46976
    if (!smem_set) {
        cudaFuncSetAttribute(edge_kernel, cudaFuncAttributeMaxDynamicSharedMemorySize, smem_bytes);
        smem_set = 1;
    }

    const int n4 = N * 288;
    const int prep_blocks = 46 + (n4 + 255) / 256;
    prep_kernel<<<prep_blocks, 256>>>(Wr0, Wr1, Wr2, Wr3, n4);
    up_kernel<<<(N + 7) / 8, 288>>>(f_in, Wu0, Wu1, Wu2, N);
    edge_kernel<<<(E + 31) / 32, 256, smem_bytes>>>(pos, batch, esrc, edst, shifts, cell, E);
    out_kernel<<<(N + 7) / 8, 288>>>(Wo0, Wo1, Wo2, (float*)d_out, N);
}

// round 17
// speedup vs baseline: 1.0214x; 1.0214x over previous
#include <cuda_runtime.h>
#include <math.h>

#define MAXN 10000

// ---------------- device scratch --------------------------------------------
__device__ float    g_cst;                     // CST_SILU
__device__ float    g_xs[MAXN * 288];          // up-projected node features, [node][slot 0..8][u 0..31]
__device__ float4   g_mid4[MAXN * 288];        // aggregated messages, 1152 f/node
__device__ unsigned g_w3f[8 * 44 * 32 * 2];    // Wr3/8 tf32 B-frags: [nt][ktp 0..3][lane] uint4
__device__ float    g_wr0p[4 * 128];           // Wr0 row-pair packed
__device__ float    g_wr1p[32 * 128];          // Wr1 row-pair packed
__device__ float    g_wr2p[32 * 128];          // Wr2 row-pair packed

// row-pair packing: p[j2*128 + lane*4 + c]:
//   c0 = W[2j2][2*lane], c1 = W[2j2][2*lane+1], c2 = W[2j2+1][2*lane], c3 = W[2j2+1][2*lane+1]
// g_w3f uint4 at ((nt*4+ktp)*32+lane): {b0(kt=2ktp), b1(2ktp), b0(2ktp+1), b1(2ktp+1)}
//
// g_xs per-node layout (288 floats): slot*32 + u, slot = {x0, x1_0..2, x2_0..4}
// g_mid per-node layout (1152 floats), u-major float4 groups:
//   blk0 A:    u*4 + {p0, p1, p2, p74}
//   blk1..4 B: 128 + q*128 + u*4 + {x, y, z, extra_q}, extra = {p84, p94, pa4, 0}
//   blk5..8 C: 640 + r*128 + u*4 + c

typedef unsigned long long ull;

__device__ __forceinline__ float silu_f(float v) {
    return __fdividef(v, 1.0f + __expf(-v));
}

#define FFMA2(d, a, b) asm("fma.rn.f32x2 %0, %1, %2, %3;" : "=l"(d) : "l"(a), "l"(b), "l"(d))

__device__ __forceinline__ float2 upk(ull v) {
    float2 r;
    asm("mov.b64 {%0, %1}, %2;" : "=f"(r.x), "=f"(r.y) : "l"(v));
    return r;
}

__device__ __forceinline__ unsigned tf32_rna(float x) {
    unsigned u;
    asm("cvt.rna.tf32.f32 %0, %1;" : "=r"(u) : "f"(x));
    return u;
}

__device__ __forceinline__ void mma_tf32(float& c0, float& c1, float& c2, float& c3,
                                         unsigned a0, unsigned a1, unsigned a2, unsigned a3,
                                         unsigned b0, unsigned b1) {
    asm volatile(
        "mma.sync.aligned.m16n8k8.row.col.f32.tf32.tf32.f32 "
        "{%0,%1,%2,%3},{%4,%5,%6,%7},{%8,%9},{%0,%1,%2,%3};"
        : "+f"(c0), "+f"(c1), "+f"(c2), "+f"(c3)
        : "r"(a0), "r"(a1), "r"(a2), "r"(a3), "r"(b0), "r"(b1));
}

// ---------------- fused prep -------------------------------------------------
// b=0: cst | b in [1,44]: w3f repack | b=45: Wr0/1/2 row-pair repack | b>=46: zero mid
__global__ void prep_kernel(const float* __restrict__ Wr0,
                            const float* __restrict__ Wr1,
                            const float* __restrict__ Wr2,
                            const float* __restrict__ Wr3, int n4zero) {
    const int b = blockIdx.x;
    const int t = threadIdx.x;  // 256

    if (b == 0) {
        __shared__ double red[256];
        const int NI = 4096;
        const double h = 24.0 / NI;
        double s = 0.0;
        for (int i = t; i <= NI; i += 256) {
            double xx = -12.0 + h * i;
            double sig = 1.0 / (1.0 + exp(-xx));
            double f = xx * sig;
            f = f * f * exp(-0.5 * xx * xx);
            double c = (i == 0 || i == NI) ? 1.0 : ((i & 1) ? 4.0 : 2.0);
            s += c * f;
        }
        red[t] = s;
        __syncthreads();
        for (int o = 128; o > 0; o >>= 1) {
            if (t < o) red[t] += red[t + o];
            __syncthreads();
        }
        if (t == 0) {
            double I = red[0] * h / 3.0 / 2.5066282746310005024;
            g_cst = (float)(1.0 / sqrt(I));
        }
    } else if (b <= 44) {
        const int f = (b - 1) * 256 + t;   // (kt*44 + nt)*32 + lane
        if (f < 8 * 44 * 32) {
            const int lane = f & 31;
            const int pair = f >> 5;
            const int nt = pair % 44;
            const int kt = pair / 44;
            const int tig = lane & 3;
            const int gid = lane >> 2;
            const int n = nt * 8 + gid;
            float w0 = Wr3[(kt * 8 + tig) * 352 + n] * 0.125f;
            float w1 = Wr3[(kt * 8 + tig + 4) * 352 + n] * 0.125f;
            const int ktp = kt >> 1;
            const int o = (((nt * 4 + ktp) * 32 + lane) << 2) + ((kt & 1) << 1);
            g_w3f[o + 0] = tf32_rna(w0);
            g_w3f[o + 1] = tf32_rna(w1);
        }
    } else if (b == 45) {
        // Wr0/1/2 row-pair repack: 512 + 4096 + 4096 = 8704 elements
        for (int idx = t; idx < 8704; idx += 256) {
            const float* W;
            float* P;
            int li;
            if (idx < 512)       { W = Wr0; P = g_wr0p; li = idx; }
            else if (idx < 4608) { W = Wr1; P = g_wr1p; li = idx - 512; }
            else                 { W = Wr2; P = g_wr2p; li = idx - 4608; }
            const int j2 = li >> 7, q = li & 127;
            const int lane = q >> 2, c = q & 3;
            const int row = 2 * j2 + (c >> 1);
            const int col = 2 * lane + (c & 1);
            P[li] = W[row * 64 + col];
        }
    } else {
        const int i = (b - 46) * 256 + t;
        if (i < n4zero) g_mid4[i] = make_float4(0.f, 0.f, 0.f, 0.f);
    }
}

// ---------------- node up-projection (8 nodes/block, slot-major) ------------
__global__ void up_kernel(const float* __restrict__ f_in,
                          const float* __restrict__ Wu0,
                          const float* __restrict__ Wu1,
                          const float* __restrict__ Wu2, int N) {
    const int n0 = blockIdx.x * 8;
    const int t = threadIdx.x;  // 288
    __shared__ float fs[8][288];
    const int nmax = (N - n0 < 8) ? (N - n0) : 8;
#pragma unroll 1
    for (int j = t; j < nmax * 288; j += 288)
        fs[j / 288][j % 288] = f_in[n0 * 288 + j];
    __syncthreads();

    const int slot = t >> 5;
    const int w = t & 31;
    int i, off, d;
    const float* W;
    if (slot == 0)      { i = 0;        d = 1; off = 0;   W = Wu0; }
    else if (slot < 4)  { i = slot - 1; d = 3; off = 32;  W = Wu1; }
    else                { i = slot - 4; d = 5; off = 128; W = Wu2; }

    float acc[8] = {0.f, 0.f, 0.f, 0.f, 0.f, 0.f, 0.f, 0.f};
#pragma unroll 4
    for (int u = 0; u < 32; u++) {
        float wt = __ldg(W + u * 32 + w);
        const int fi = off + u * d + i;
#pragma unroll
        for (int e = 0; e < 8; e++)
            acc[e] = fmaf(fs[e][fi], wt, acc[e]);
    }
#pragma unroll
    for (int e = 0; e < nmax; e++)
        g_xs[(n0 + e) * 288 + slot * 32 + w] = acc[e] * 0.17677669529663687f;
}

// ---------------- radial MLP 64->64 layer (4 edges, packed weights) ---------
__device__ __forceinline__ void mlp64d(const float* __restrict__ in2,
                                       float* __restrict__ out2,
                                       const float* __restrict__ Wp,
                                       int lane, float cst) {
    ull accA[4] = {0ull,0ull,0ull,0ull};
    ull accB[4] = {0ull,0ull,0ull,0ull};
    const ulonglong2* Wpp = reinterpret_cast<const ulonglong2*>(Wp + lane * 4);
#pragma unroll 4
    for (int j2 = 0; j2 < 32; j2++) {
        ulonglong2 wp = __ldg(Wpp + j2 * 32);   // one LDG.128, 512B contiguous per warp
#pragma unroll
        for (int e = 0; e < 4; e++) {
            ulonglong2 hp = *reinterpret_cast<const ulonglong2*>(in2 + e * 128 + 4 * j2);
            FFMA2(accA[e], wp.x, hp.x);
            FFMA2(accB[e], wp.y, hp.y);
        }
    }
#pragma unroll
    for (int e = 0; e < 4; e++) {
        float2 va = upk(accA[e]);
        float2 vb = upk(accB[e]);
        float v0 = silu_f((va.x + vb.x) * 0.125f) * cst;
        float v1 = silu_f((va.y + vb.y) * 0.125f) * cst;
        *reinterpret_cast<float4*>(out2 + e * 128 + 4 * lane) = make_float4(v0, v0, v1, v1);
    }
}

// smem layout (floats)  (round-15 validated: hfr NOT aliased, two barriers):
//   wsm  [0, 11584)        phase-2 radial weights: [32 edges][stride 362]
//        (phase-1 hA2/hB2 [0,8192) alias under wsm; dead before wsm written)
//   hfr  [11584, 13696)    A-fragments: [etile 2][kt 8][reg 4][33]
//   geo  [13696, 13856)    per-warp edge state: [8 warps][4 edges][5]
#define SM_HA 0
#define SM_HB 4096
#define SM_HF 11584
#define SM_GEO 13696
#define WS_STRIDE 362
#define SM_TOTAL_F 13856

// ---------------- fused per-edge kernel (block = 32 edges) ------------------
__global__ void __launch_bounds__(256, 3) edge_kernel(
    const float* __restrict__ pos, const int* __restrict__ batch,
    const int* __restrict__ esrc, const int* __restrict__ edst,
    const float* __restrict__ shifts, const float* __restrict__ cell, int E)
{
    extern __shared__ float sm[];
    const int wid  = threadIdx.x >> 5;
    const int lane = threadIdx.x & 31;
    float* hA2 = sm + SM_HA + wid * 512;
    float* hB2 = sm + SM_HB + wid * 512;
    unsigned* hfr = reinterpret_cast<unsigned*>(sm + SM_HF);
    float* geo = sm + SM_GEO + wid * 20;   // [4 edges][5]
    float* wsm = sm;                       // aliases hA2/hB2 after phase 1

    const int base = blockIdx.x * 32 + wid * 4;
    const int etile = wid >> 2;
    const float cst = g_cst;

    // ================= phase 1: geometry + radial MLP layers 1-3 ============
    {
        float Lr[4];
#pragma unroll
        for (int e = 0; e < 4; e++) {
            int ei = (base + e < E) ? base + e : E - 1;
            const int src = __ldg(esrc + ei);
            const int dst = __ldg(edst + ei);
            const float sx = __ldg(shifts + 3*ei), sy = __ldg(shifts + 3*ei+1), sz = __ldg(shifts + 3*ei+2);
            const float* Cc = cell + 9 * __ldg(batch + src);
            float vx = __ldg(pos+3*dst+0) - __ldg(pos+3*src+0) + sx*__ldg(Cc+0) + sy*__ldg(Cc+3) + sz*__ldg(Cc+6);
            float vy = __ldg(pos+3*dst+1) - __ldg(pos+3*src+1) + sx*__ldg(Cc+1) + sy*__ldg(Cc+4) + sz*__ldg(Cc+7);
            float vz = __ldg(pos+3*dst+2) - __ldg(pos+3*src+2) + sx*__ldg(Cc+2) + sy*__ldg(Cc+5) + sz*__ldg(Cc+8);
            float L = sqrtf(vx*vx + vy*vy + vz*vz);
            float inv = 1.0f / fmaxf(L, 1e-12f);
            Lr[e] = L;
            if (lane == 0) {
                geo[e * 5 + 0] = vx * inv;
                geo[e * 5 + 1] = vy * inv;
                geo[e * 5 + 2] = vz * inv;
                geo[e * 5 + 3] = __int_as_float(src);
                geo[e * 5 + 4] = __int_as_float(dst);
            }
        }

        const int k = lane & 7;
        const int e = lane >> 3;
        float Ls = Lr[0];
        if (e == 1) Ls = Lr[1]; else if (e == 2) Ls = Lr[2]; else if (e == 3) Ls = Lr[3];
        float tt = (Ls - (float)(k + 1) * (5.0f / 9.0f)) * 1.8f;
        float v = __expf(-tt * tt) * 2.525381361380527f;  // sqrt(8)/1.12
        *reinterpret_cast<float2*>(hB2 + e * 128 + 2 * k) = make_float2(v, v);
    }
    __syncwarp();

    // layer 1: 8 -> 64 (hB2 -> hA2), packed weights
    {
        ull acc[4] = {0ull,0ull,0ull,0ull};
        const ulonglong2* Wpp = reinterpret_cast<const ulonglong2*>(g_wr0p + lane * 4);
#pragma unroll
        for (int j2 = 0; j2 < 4; j2++) {
            ulonglong2 wp = __ldg(Wpp + j2 * 32);
#pragma unroll
            for (int e = 0; e < 4; e++) {
                ulonglong2 hp = *reinterpret_cast<const ulonglong2*>(hB2 + e * 128 + 4 * j2);
                FFMA2(acc[e], wp.x, hp.x);
                FFMA2(acc[e], wp.y, hp.y);
            }
        }
#pragma unroll
        for (int e = 0; e < 4; e++) {
            float2 v = upk(acc[e]);
            float v0 = silu_f(v.x * 0.35355339059327373f) * cst;
            float v1 = silu_f(v.y * 0.35355339059327373f) * cst;
            *reinterpret_cast<float4*>(hA2 + e * 128 + 4 * lane) = make_float4(v0, v0, v1, v1);
        }
    }
    __syncwarp();
    mlp64d(hA2, hB2, g_wr1p, lane, cst);   // layer 2
    __syncwarp();

    // layer 3: read hB2, write h into A-fragment layout (tf32 bits)
    {
        ull accA[4] = {0ull,0ull,0ull,0ull};
        ull accB[4] = {0ull,0ull,0ull,0ull};
        const ulonglong2* Wpp = reinterpret_cast<const ulonglong2*>(g_wr2p + lane * 4);
#pragma unroll 4
        for (int j2 = 0; j2 < 32; j2++) {
            ulonglong2 wp = __ldg(Wpp + j2 * 32);
#pragma unroll
            for (int e = 0; e < 4; e++) {
                ulonglong2 hp = *reinterpret_cast<const ulonglong2*>(hB2 + e * 128 + 4 * j2);
                FFMA2(accA[e], wp.x, hp.x);
                FFMA2(accB[e], wp.y, hp.y);
            }
        }
#pragma unroll
        for (int e = 0; e < 4; e++) {
            float2 va = upk(accA[e]);
            float2 vb = upk(accB[e]);
            float v0 = silu_f((va.x + vb.x) * 0.125f) * cst;
            float v1 = silu_f((va.y + vb.y) * 0.125f) * cst;
            const int m = (wid & 3) * 4 + e;
#pragma unroll
            for (int cc = 0; cc < 2; cc++) {
                int k  = 2 * lane + cc;
                float v = cc ? v1 : v0;
                int kt  = k >> 3;
                int kin = k & 7;
                int reg = ((m >= 8) ? 1 : 0) + ((kin >= 4) ? 2 : 0);
                int lp  = (m & 7) * 4 + (kin & 3);
                hfr[((etile * 8 + kt) * 4 + reg) * 33 + lp] = tf32_rna(v);
            }
        }
    }
    __syncthreads();   // hfr complete across etile; hA2/hB2 reads all done

    // ================= MMA pass: all 44 n-tiles =============================
    {
        unsigned afr[8][4];
#pragma unroll
        for (int kt = 0; kt < 8; kt++)
#pragma unroll
            for (int r = 0; r < 4; r++)
                afr[kt][r] = hfr[((etile * 8 + kt) * 4 + r) * 33 + lane];

        const int nch = wid & 3;
        const int gid = lane >> 2;
        const int tig = lane & 3;
        const uint4* Bf4 = reinterpret_cast<const uint4*>(g_w3f);
#pragma unroll 1
        for (int tt = 0; tt < 11; tt++) {
            const int nt = nch * 11 + tt;
            float c0 = 0.f, c1 = 0.f, c2 = 0.f, c3 = 0.f;
#pragma unroll
            for (int ktp = 0; ktp < 4; ktp++) {
                uint4 q = __ldg(Bf4 + (nt * 4 + ktp) * 32 + lane);  // 512B contiguous/warp
                mma_tf32(c0, c1, c2, c3,
                         afr[2*ktp][0], afr[2*ktp][1], afr[2*ktp][2], afr[2*ktp][3],
                         q.x, q.y);
                mma_tf32(c0, c1, c2, c3,
                         afr[2*ktp+1][0], afr[2*ktp+1][1], afr[2*ktp+1][2], afr[2*ktp+1][3],
                         q.z, q.w);
            }
            const int col = nt * 8 + tig * 2;
            float* r0 = wsm + (etile * 16 + gid) * WS_STRIDE + col;
            *reinterpret_cast<float2*>(r0) = make_float2(c0, c1);
            *reinterpret_cast<float2*>(r0 + 8 * WS_STRIDE) = make_float2(c2, c3);
        }
    }
    __syncthreads();

    // ================= TP + 9 coalesced vector atomics ======================
    // software-pipelined: prefetch edge e+1's 9 x-feature LDGs before edge e's
    // compute+atomics (geo holds clamped src indices, so prefetch is always safe)
    const float A_  = 0.31622776601683794f;  // 1/sqrt(10)
    const float B_  = 0.18257418583505536f;  // 1/sqrt(30)
    const float AL  = 0.11952286093343936f;  // 1/sqrt(70)
    const float BE  = 0.20701966780270626f;  // sqrt(3/70)
    const float SQ3 = 1.7320508075688772f;
    const float SQ5 = 2.23606797749979f;

    float xv0, xv1, xv2, xv3, xv4, xv5, xv6, xv7, xv8;
    {
        const int src0 = __float_as_int(geo[3]);
        const float* xp = g_xs + src0 * 288 + lane;
        xv0 = __ldg(xp);        xv1 = __ldg(xp + 32);  xv2 = __ldg(xp + 64);
        xv3 = __ldg(xp + 96);   xv4 = __ldg(xp + 128); xv5 = __ldg(xp + 160);
        xv6 = __ldg(xp + 192);  xv7 = __ldg(xp + 224); xv8 = __ldg(xp + 256);
    }

#pragma unroll
    for (int e = 0; e < 4; e++) {
        if (base + e >= E) break;
        const float ux = geo[e * 5 + 0];
        const float uy = geo[e * 5 + 1];
        const float uz = geo[e * 5 + 2];
        const int dst = __float_as_int(geo[e * 5 + 4]);

        // consume prefetched features, then immediately issue next edge's loads
        const float x0 = xv0;
        const float x10 = xv1, x11 = xv2, x12 = xv3;
        const float x20 = xv4, x21 = xv5, x22 = xv6, x23 = xv7, x24 = xv8;
        if (e < 3) {
            const int srcn = __float_as_int(geo[(e + 1) * 5 + 3]);
            const float* xpn = g_xs + srcn * 288 + lane;
            xv0 = __ldg(xpn);       xv1 = __ldg(xpn + 32);  xv2 = __ldg(xpn + 64);
            xv3 = __ldg(xpn + 96);  xv4 = __ldg(xpn + 128); xv5 = __ldg(xpn + 160);
            xv6 = __ldg(xpn + 192); xv7 = __ldg(xpn + 224); xv8 = __ldg(xpn + 256);
        }

        const float s1x = SQ3 * ux, s1y = SQ3 * uy, s1z = SQ3 * uz;
        const float s20 = 3.872983346207417f * ux * uz;
        const float s21 = 3.872983346207417f * ux * uy;
        const float s22 = SQ5 * (uy*uy - 0.5f*(ux*ux + uz*uz));
        const float s23 = 3.872983346207417f * uy * uz;
        const float s24 = 1.9364916731037085f * (uz*uz - ux*ux);

        const float* wrow = wsm + (wid * 4 + e) * WS_STRIDE + lane;
        float w[11];
#pragma unroll
        for (int k = 0; k < 11; k++) w[k] = wrow[k * 32];

        // l0
        const float p0 = x0 * w[0];
        const float p1 = 0.5773502691896258f * (x10*s1x + x11*s1y + x12*s1z) * w[1];
        const float p2 = 0.4472135954999579f * (x20*s20 + x21*s21 + x22*s22 + x23*s23 + x24*s24) * w[2];

        // l1
        const float c3 = x0 * w[3];
        float p5x, p5y, p5z;
        {
            float wv = SQ3 * w[5];
            float B00 = -B_*s22 - A_*s24;
            float B01 =  A_*s21;
            float B02 =  A_*s20;
            float B11 =  2.f*B_*s22;
            float B12 =  A_*s23;
            float B22 = -B_*s22 + A_*s24;
            p5x = wv * (x10*B00 + x11*B01 + x12*B02);
            p5y = wv * (x10*B01 + x11*B11 + x12*B12);
            p5z = wv * (x10*B02 + x11*B12 + x12*B22);
        }
        float p6x, p6y, p6z;
        {
            float wv = SQ3 * w[6];
            p6x = wv * (A_*(x20*s1z + x21*s1y) - B_*x22*s1x - A_*x24*s1x);
            p6y = wv * (A_*(x21*s1x + x23*s1z) + 2.f*B_*x22*s1y);
            p6z = wv * (A_*(x20*s1x + x23*s1y + x24*s1z) - B_*x22*s1z);
        }

        // l2
        const float c7 = x0 * w[7];
        const float p70 = c7*s20, p71 = c7*s21, p72 = c7*s22, p73 = c7*s23, p74 = c7*s24;
        float p80, p81, p82, p83, p84;
        {
            float wv = SQ5 * w[8];
            p80 = wv * (A_*(x10*s1z + x12*s1x));
            p81 = wv * (A_*(x10*s1y + x11*s1x));
            p82 = wv * (B_*(-x10*s1x + 2.f*x11*s1y - x12*s1z));
            p83 = wv * (A_*(x11*s1z + x12*s1y));
            p84 = wv * (A_*(-x10*s1x + x12*s1z));
        }
        const float p90 = x20*w[9], p91 = x21*w[9], p92 = x22*w[9], p93 = x23*w[9], p94 = x24*w[9];
        float pa0, pa1, pa2, pa3, pa4;
        {
            float wv = SQ5 * w[10];
            pa0 = wv * (x20*(2.f*AL*s22) + x21*(-BE*s23) + x22*(2.f*AL*s20) + x23*(-BE*s21));
            pa1 = wv * (x20*(-BE*s23) + x21*(-AL*s22 + BE*s24) + x22*(-AL*s21) + x23*(-BE*s20) + x24*(BE*s21));
            pa2 = wv * (x20*(2.f*AL*s20) + x21*(-AL*s21) + x22*(-2.f*AL*s22) + x23*(-AL*s23) + x24*(2.f*AL*s24));
            pa3 = wv * (x20*(-BE*s21) + x21*(-BE*s20) + x22*(-AL*s23) + x23*(-AL*s22 - BE*s24) + x24*(-BE*s23));
            pa4 = wv * (x21*(BE*s21) + x22*(2.f*AL*s24) + x23*(-BE*s23) + x24*(2.f*AL*s22));
        }

        float4* mb = reinterpret_cast<float4*>(reinterpret_cast<float*>(g_mid4) + dst * 1152) + lane;
        atomicAdd(mb,       make_float4(p0, p1, p2, p74));
        atomicAdd(mb + 32,  make_float4(c3*s1x, c3*s1y, c3*s1z, p84));
        atomicAdd(mb + 64,  make_float4(x10*w[4], x11*w[4], x12*w[4], p94));
        atomicAdd(mb + 96,  make_float4(p5x, p5y, p5z, pa4));
        atomicAdd(mb + 128, make_float4(p6x, p6y, p6z, 0.f));
        atomicAdd(mb + 160, make_float4(p70, p71, p72, p73));
        atomicAdd(mb + 192, make_float4(p80, p81, p82, p83));
        atomicAdd(mb + 224, make_float4(p90, p91, p92, p93));
        atomicAdd(mb + 256, make_float4(pa0, pa1, pa2, pa3));
    }
}

// ---------------- per-node output projection (8 nodes/block, transposed) ----
__global__ void out_kernel(const float* __restrict__ Wo0,
                           const float* __restrict__ Wo1,
                           const float* __restrict__ Wo2,
                           float* __restrict__ out, int N) {
    const int n0 = blockIdx.x * 8;
    const int t = threadIdx.x;  // 288
    __shared__ float ms[8][1152];
    const int nmax = (N - n0 < 8) ? (N - n0) : 8;
#pragma unroll 1
    for (int j = t; j < nmax * 288; j += 288) {
        const int node = j / 288, jj = j % 288;
        float4 v = g_mid4[(n0 + node) * 288 + jj];
        const int blk = jj >> 5, u = jj & 31;
        float* b = ms[node] + (blk * 4) * 32 + u;
        b[0]  = v.x;
        b[32] = v.y;
        b[64] = v.z;
        b[96] = v.w;
    }
    __syncthreads();

    const int slot = t >> 5;
    const int w = t & 31;
    float acc[8] = {0.f, 0.f, 0.f, 0.f, 0.f, 0.f, 0.f, 0.f};
    int off, d, i;
    float scale;

    #define OUT_ACC(Wp, grp, sidx)                                             \
        do {                                                                   \
            const float4* mrow[8];                                             \
            _Pragma("unroll")                                                  \
            for (int e = 0; e < 8; e++)                                        \
                mrow[e] = reinterpret_cast<const float4*>(ms[e] + (sidx) * 32);\
            _Pragma("unroll")                                                  \
            for (int u4 = 0; u4 < 8; u4++) {                                   \
                float4 mv[8];                                                  \
                _Pragma("unroll")                                              \
                for (int e = 0; e < 8; e++) mv[e] = mrow[e][u4];               \
                _Pragma("unroll")                                              \
                for (int c = 0; c < 4; c++) {                                  \
                    float wt = __ldg(Wp + ((grp) * 32 + u4 * 4 + c) * 32 + w); \
                    _Pragma("unroll")                                          \
                    for (int e = 0; e < 8; e++) {                              \
                        float mval = (c == 0) ? mv[e].x : (c == 1) ? mv[e].y   \
                                   : (c == 2) ? mv[e].z : mv[e].w;             \
                        acc[e] = fmaf(mval, wt, acc[e]);                       \
                    }                                                          \
                }                                                              \
            }                                                                  \
        } while (0)

    if (slot == 0) {
        off = 0; d = 1; i = 0;
        scale = 0.006378879538497859f;   // 1/(sqrt(96)*16)
#pragma unroll
        for (int s = 0; s < 3; s++)
            OUT_ACC(Wo0, s, s);
    } else if (slot < 4) {
        off = 32; d = 3; i = slot - 1;
        scale = 0.005524271728019903f;   // 1/(sqrt(128)*16)
#pragma unroll
        for (int q = 0; q < 4; q++)
            OUT_ACC(Wo1, q, 4 + q * 4 + i);
    } else {
        off = 128; d = 5; i = slot - 4;
        scale = 0.005524271728019903f;
        if (i < 4) {
#pragma unroll
            for (int r = 0; r < 4; r++)
                OUT_ACC(Wo2, r, 20 + r * 4 + i);
        } else {
#pragma unroll
            for (int r = 0; r < 4; r++)
                OUT_ACC(Wo2, r, 4 * r + 3);
        }
    }
    #undef OUT_ACC

#pragma unroll
    for (int e = 0; e < nmax; e++)
        out[(n0 + e) * 288 + off + w * d + i] = acc[e] * scale;
}

// ---------------- launch -----------------------------------------------------
extern "C" void kernel_launch(void* const* d_in, const int* in_sizes, int n_in,
                              void* d_out, int out_size) {
    const float* f_in   = (const float*)d_in[0];
    const float* pos    = (const float*)d_in[1];
    const int*   batch  = (const int*)d_in[2];
    const int*   esrc   = (const int*)d_in[3];
    const int*   edst   = (const int*)d_in[4];
    const float* shifts = (const float*)d_in[5];
    const float* cell   = (const float*)d_in[6];
    const int wb = n_in - 10;
    const float* Wu0 = (const float*)d_in[wb + 0];
    const float* Wu1 = (const float*)d_in[wb + 1];
    const float* Wu2 = (const float*)d_in[wb + 2];
    const float* Wr0 = (const float*)d_in[wb + 3];
    const float* Wr1 = (const float*)d_in[wb + 4];
    const float* Wr2 = (const float*)d_in[wb + 5];
    const float* Wr3 = (const float*)d_in[wb + 6];
    const float* Wo0 = (const float*)d_in[wb + 7];
    const float* Wo1 = (const float*)d_in[wb + 8];
    const float* Wo2 = (const float*)d_in[wb + 9];

    const int N = in_sizes[0] / 288;
    const int E = in_sizes[3];

    static int smem_set = 0;
    const int smem_bytes = SM_TOTAL_F * 4;  // 55424
    if (!smem_set) {
        cudaFuncSetAttribute(edge_kernel, cudaFuncAttributeMaxDynamicSharedMemorySize, smem_bytes);
        smem_set = 1;
    }

    const int n4 = N * 288;
    const int prep_blocks = 46 + (n4 + 255) / 256;
    prep_kernel<<<prep_blocks, 256>>>(Wr0, Wr1, Wr2, Wr3, n4);
    up_kernel<<<(N + 7) / 8, 288>>>(f_in, Wu0, Wu1, Wu2, N);
    edge_kernel<<<(E + 31) / 32, 256, smem_bytes>>>(pos, batch, esrc, edst, shifts, cell, E);
    out_kernel<<<(N + 7) / 8, 288>>>(Wo0, Wo1, Wo2, (float*)d_out, N);
}